// round 8
// baseline (speedup 1.0000x reference)
#include <cuda_runtime.h>

#define DPRED    84
#define NCLS     80
#define MAXB     8
#define MAXA     76725
#define NBINS    4096
#define KMAX     512
#define KTARGET  128
#define MAXDET   100
#define CONF_T   0.05f
#define IOU_T    0.5f
#define NMS_NT   256
#define DT       128          // decode tile = threads per decode block
#define ROWPAD   85           // 84 + 1 pad -> conflict-free smem rows

typedef unsigned long long u64;

// ---------------- device scratch (no allocation allowed) ----------------
__device__ float4 g_boxes8[MAXB * MAXA * 2];  // cx,cy,w,h | cls,conf,0,0
__device__ float  g_scores[MAXB * MAXA];      // conf if >= CONF_T else 0
__device__ int    g_hist[MAXB * NBINS];       // zero-init; re-zeroed by thresh
__device__ float  g_thresh[MAXB];
__device__ int    g_cnt[MAXB];
__device__ int    g_cand[MAXB * KMAX];

// ---------------- decode: smem-staged, thread per anchor ----------------
__global__ void __launch_bounds__(DT)
decode_kernel(const float* __restrict__ pred,
              const float* __restrict__ anchors,
              int B, int A, int total) {
    __shared__ float sbuf[DT * ROWPAD];

    int tile = blockIdx.x * DT;
    int rows = total - tile; if (rows > DT) rows = DT;

    // stage tile: fully coalesced float4 gmem reads
    const float4* src = reinterpret_cast<const float4*>(pred + (size_t)tile * DPRED);
    int nf4 = rows * (DPRED / 4);
    for (int f = threadIdx.x; f < nf4; f += DT) {
        float4 v = __ldg(src + f);
        int r  = f / (DPRED / 4);
        int c4 = f - r * (DPRED / 4);
        float* dst = &sbuf[r * ROWPAD + c4 * 4];
        dst[0] = v.x; dst[1] = v.y; dst[2] = v.z; dst[3] = v.w;
    }
    __syncthreads();

    int t = threadIdx.x;
    if (t < rows) {
        const float* row = &sbuf[t * ROWPAD];
        float v0 = row[0], v1 = row[1], v2 = row[2], v3 = row[3];

        // branchless first-occurrence argmax over 80 logits
        float best = row[4];
        int   cls  = 0;
#pragma unroll
        for (int j = 1; j < NCLS; j++) {
            float c = row[4 + j];
            if (c > best) { best = c; cls = j; }
        }

        int i = tile + t;
        int b = i / A;
        int a = i - b * A;

        float4 an = __ldg(reinterpret_cast<const float4*>(anchors) + a);
        float cx = v0 * 0.1f * an.z + an.x;
        float cy = v1 * 0.1f * an.w + an.y;
        float w  = expf(v2 * 0.2f) * an.z;
        float h  = expf(v3 * 0.2f) * an.w;
        float conf = 1.0f / (1.0f + expf(-best));

        g_boxes8[(size_t)i * 2 + 0] = make_float4(cx, cy, w, h);
        g_boxes8[(size_t)i * 2 + 1] = make_float4((float)cls, conf, 0.f, 0.f);

        float s = (conf >= CONF_T) ? conf : 0.0f;
        g_scores[i] = s;
        if (s > 0.0f) {
            int bin = (int)(s * (float)NBINS);
            if (bin > NBINS - 1) bin = NBINS - 1;
            if (bin < 1) bin = 1;
            atomicAdd(&g_hist[b * NBINS + bin], 1);
        }
    }
}

// ------- threshold from histogram (and re-zero hist for next call) -------
__global__ void __launch_bounds__(512)
thresh_kernel() {
    int b   = blockIdx.x;
    int tid = threadIdx.x;
    __shared__ int sh[NBINS];
    __shared__ int csum[128];          // 32-bin chunk sums

    for (int i = tid; i < NBINS; i += 512)
        sh[i] = g_hist[b * NBINS + i];
    __syncthreads();

    // re-zero for the next graph replay (deterministic pipeline state)
    for (int i = tid; i < NBINS; i += 512)
        g_hist[b * NBINS + i] = 0;

    if (tid < 128) {
        int s = 0, base = tid * 32;
#pragma unroll
        for (int j = 0; j < 32; j++) s += sh[base + j];
        csum[tid] = s;
    }
    __syncthreads();

    if (tid == 0) {
        int cum = 0, binSel = NBINS, c = 128;
        while (c > 1 && cum < KTARGET && cum + csum[c - 1] <= KMAX) {
            c--; cum += csum[c]; binSel = c * 32;
        }
        if (cum < KTARGET && c >= 1) {
            for (int bin = c * 32 - 1; bin >= (c - 1) * 32 && bin >= 1; --bin) {
                int h = sh[bin];
                if (cum + h > KMAX) break;
                cum += h; binSel = bin;
                if (cum >= KTARGET) break;
            }
        }
        g_thresh[b] = (float)binSel / (float)NBINS;
        g_cnt[b]    = 0;
    }
}

// ---------------- compact candidates: many blocks per batch --------------
__global__ void compact_kernel(int A) {
    int b = blockIdx.y;
    float th = g_thresh[b];
    const float* sc = g_scores + (size_t)b * A;
    for (int i = blockIdx.x * blockDim.x + threadIdx.x; i < A;
         i += gridDim.x * blockDim.x) {
        if (sc[i] > th) {
            int p = atomicAdd(&g_cnt[b], 1);
            if (p < KMAX) g_cand[b * KMAX + p] = i;
        }
    }
}

// ---------------- NMS: block per batch, warp-0 smem scan + REDUX --------
__global__ void __launch_bounds__(NMS_NT, 1)
nms_kernel(float* __restrict__ out, int A) {
    int b   = blockIdx.x;
    int tid = threadIdx.x;

    __shared__ u64   skey[KMAX];
    __shared__ float sx1[KMAX], sy1[KMAX], sx2[KMAX], sy2[KMAX], sar[KMAX];
    __shared__ float scx[KMAX], scy[KMAX], swd[KMAX], sht[KMAX];
    __shared__ int   scls[KMAX];
    __shared__ int   sFallback;
    __shared__ u64   sBest;
    __shared__ u64   redk[NMS_NT / 32];

    int cnt = g_cnt[b];
    bool overflow = (cnt > KMAX);
    if (cnt > KMAX) cnt = KMAX;

    for (int i = tid; i < cnt; i += NMS_NT) {
        int a = g_cand[b * KMAX + i];
        size_t base = ((size_t)b * A + a) * 2;
        float4 p0 = g_boxes8[base + 0];
        float4 p1 = g_boxes8[base + 1];
        float hw = 0.5f * p0.z, hh = 0.5f * p0.w;
        sx1[i] = p0.x - hw; sy1[i] = p0.y - hh;
        sx2[i] = p0.x + hw; sy2[i] = p0.y + hh;
        sar[i] = p0.z * p0.w;
        scx[i] = p0.x; scy[i] = p0.y; swd[i] = p0.z; sht[i] = p0.w;
        scls[i] = (int)p1.x;
        skey[i] = ((u64)__float_as_uint(p1.y) << 32) |
                  (unsigned)(0x7FFFFFFF - a);
    }
    if (tid == 0) sFallback = overflow ? 1 : 0;
    __syncthreads();

    // ---- fast path: warp 0 only, no block barriers, no atomics ----
    if (tid < 32 && !sFallback) {
        int lane = tid;
        for (int d = 0; d < MAXDET; d++) {
            u64 bk = 0; int bs = 0;
            for (int i = lane; i < cnt; i += 32) {
                u64 k = skey[i];
                if (k > bk) { bk = k; bs = i; }
            }
            unsigned hi  = (unsigned)(bk >> 32);
            unsigned mhi = __reduce_max_sync(0xffffffffu, hi);
            if (mhi == 0u) {                 // pool exhausted -> exact path
                if (lane == 0) sFallback = 1;
                break;
            }
            unsigned lo  = (hi == mhi) ? (unsigned)bk : 0u;
            unsigned mlo = __reduce_max_sync(0xffffffffu, lo);
            u64 selKey = ((u64)mhi << 32) | mlo;

            bool win = (bk == selKey);       // keys unique -> one winner
            unsigned wm = __ballot_sync(0xffffffffu, win);
            int wl   = __ffs(wm) - 1;
            int slot = __shfl_sync(0xffffffffu, bs, wl);

            float X1 = sx1[slot], Y1 = sy1[slot];    // broadcast LDS
            float X2 = sx2[slot], Y2 = sy2[slot];
            float AR = sar[slot];
            int   CL = scls[slot];

            if (lane == 0) {
                float* o = out + ((size_t)b * MAXDET + d) * 6;
                o[0] = scx[slot]; o[1] = scy[slot];
                o[2] = swd[slot]; o[3] = sht[slot];
                o[4] = (float)CL; o[5] = __uint_as_float(mhi);
            }
            for (int i = lane; i < cnt; i += 32) {
                u64 k = skey[i];
                if (k == selKey) { skey[i] = 0; continue; }
                if (k != 0 && scls[i] == CL) {
                    float iw = fminf(sx2[i], X2) - fmaxf(sx1[i], X1);
                    float ih = fminf(sy2[i], Y2) - fmaxf(sy1[i], Y1);
                    if (iw > 0.0f && ih > 0.0f) {
                        float inter = iw * ih;
                        float iou = inter / (sar[i] + AR - inter + 1e-8f);
                        if (iou > IOU_T) skey[i] = 0;
                    }
                }
            }
            __syncwarp();
        }
    }
    __syncthreads();

    // ---------------- exact full-array fallback (normally unreachable) ----
    if (sFallback) {
        float* sc = g_scores + (size_t)b * A;
        const float4* bx = g_boxes8 + (size_t)b * A * 2;
        for (int d = 0; d < MAXDET; d++) {
            u64 mk = 0;
            for (int i = tid; i < A; i += NMS_NT) {
                u64 k = ((u64)__float_as_uint(sc[i]) << 32) |
                        (unsigned)(0x7FFFFFFF - i);
                if (k > mk) mk = k;
            }
#pragma unroll
            for (int off = 16; off; off >>= 1) {
                u64 ok = __shfl_down_sync(0xffffffffu, mk, off);
                if (ok > mk) mk = ok;
            }
            if ((tid & 31) == 0) redk[tid >> 5] = mk;
            __syncthreads();
            if (tid < 32) {
                u64 k2 = (tid < NMS_NT / 32) ? redk[tid] : 0ull;
#pragma unroll
                for (int off = 16; off; off >>= 1) {
                    u64 ok = __shfl_down_sync(0xffffffffu, k2, off);
                    if (ok > k2) k2 = ok;
                }
                if (tid == 0) sBest = k2;
            }
            __syncthreads();
            u64 selKey = sBest;
            int   a = 0x7FFFFFFF - (int)(selKey & 0xFFFFFFFFull);
            float selScore = __uint_as_float((unsigned)(selKey >> 32));
            float4 p0 = bx[(size_t)a * 2 + 0];
            float4 p1 = bx[(size_t)a * 2 + 1];
            float X1 = p0.x - 0.5f * p0.z, Y1 = p0.y - 0.5f * p0.w;
            float X2 = p0.x + 0.5f * p0.z, Y2 = p0.y + 0.5f * p0.w;
            float AR = p0.z * p0.w;
            int   CL = (int)p1.x;
            if (tid == 0) {
                float* o = out + ((size_t)b * MAXDET + d) * 6;
                o[0] = p0.x; o[1] = p0.y; o[2] = p0.z;
                o[3] = p0.w; o[4] = p1.x; o[5] = selScore;
            }
            __syncthreads();
            for (int i = tid; i < A; i += NMS_NT) {
                if (i == a) { sc[i] = 0.0f; continue; }
                if (sc[i] == 0.0f) continue;
                float4 q0 = bx[(size_t)i * 2 + 0];
                float4 q1 = bx[(size_t)i * 2 + 1];
                if ((int)q1.x == CL) {
                    float iw = fminf(q0.x + 0.5f * q0.z, X2) - fmaxf(q0.x - 0.5f * q0.z, X1);
                    float ih = fminf(q0.y + 0.5f * q0.w, Y2) - fmaxf(q0.y - 0.5f * q0.w, Y1);
                    if (iw > 0.0f && ih > 0.0f) {
                        float inter = iw * ih;
                        float iou = inter / (q0.z * q0.w + AR - inter + 1e-8f);
                        if (iou > IOU_T) sc[i] = 0.0f;
                    }
                }
            }
            __syncthreads();
        }
    }
}

// ---------------- launch ----------------
extern "C" void kernel_launch(void* const* d_in, const int* in_sizes, int n_in,
                              void* d_out, int out_size) {
    const float *pred, *anch;
    int s0 = in_sizes[0], s1 = in_sizes[1];
    if (s0 >= s1) {
        pred = (const float*)d_in[0]; anch = (const float*)d_in[1];
    } else {
        pred = (const float*)d_in[1]; anch = (const float*)d_in[0];
        int t = s0; s0 = s1; s1 = t;
    }
    int A = s1 / 4;
    int B = out_size / (MAXDET * 6);
    int total = B * A;

    decode_kernel<<<(total + DT - 1) / DT, DT>>>(pred, anch, B, A, total);
    thresh_kernel<<<B, 512>>>();
    compact_kernel<<<dim3(32, B), 256>>>(A);
    nms_kernel<<<B, NMS_NT>>>((float*)d_out, A);
}